// round 13
// baseline (speedup 1.0000x reference)
#include <cuda_runtime.h>
#include <stdint.h>

// Problem constants (SHAPE = (16,1,1024,1024), RATIO = 0.25)
#define N_TOTAL   16777216
#define N_VEC     (N_TOTAL / 4)
#define K_SEL     4194304u
#define GRID      296               // 2 blocks x 148 SMs -> all co-resident
#define TPB       1024
#define FULL      0xFFFFFFFFu
#define HBINS     8192              // sample histogram bins = bits[30:18]
#define H2BINS    4096              // refinement histogram: window bits [b:b-11]
#define N_SAMP    (GRID * TPB)      // 303104 samples
// K_s = N_SAMP/4 = 75776, sigma = sqrt(N_SAMP*3/16) = 238; +-12 sigma = 2861
#define R_HI      72915u            // sample-rank (from top) for T_hi
#define R_LO      78637u            // sample-rank for T_lo

// Device-global state (statically zero-initialized; finalizer re-zeroes)
__device__ __align__(16) uint32_t g_hist[HBINS];
__device__ __align__(16) uint32_t g_h2[H2BINS];
__device__ uint32_t g_Tlo, g_Thi;
__device__ uint32_t g_winReady;
__device__ uint32_t g_cntAbove;                  // # elements >= T_hi
__device__ double   g_sum;                       // exact sum of elements >= T_hi
__device__ uint32_t g_doneS, g_doneM;            // completion counters

// ---------------------------------------------------------------------------
__device__ __forceinline__ float bce_loss(float x, float t) {
    // max(x,0) - x*t + log1p(exp(-|x|)); always >= 0 for t in [0,1)
    float e = __expf(-fabsf(x));
    float base = fmaf(-x, t, fmaxf(x, 0.0f));
    float l = base + __logf(1.0f + e);
    return fmaxf(l, 0.0f);   // keep sign bit 0 -> uint order == float order
}

// b = highest bit where window values can differ (clamped >= 11).
// All window v share bits [31:b+1] == pfx0; histogram indexes bits [b:b-11].
__device__ __forceinline__ void win_params(uint32_t Tlo, uint32_t Thi,
                                           uint32_t& pfx0, int& s3) {
    uint32_t m = Tlo ^ (Thi - 1u);
    int b = m ? (31 - __clz((int)m)) : 11;
    if (b < 11) b = 11;
    s3 = b - 11;                       // bin width = 2^s3 ulps
    pfx0 = Tlo >> (b + 1);
}

// ---------------------------------------------------------------------------
// kfused: one persistent kernel, three phases.
//  S: sample -> coarse histogram -> last block derives window, sets flag
//  B: lean full streaming pass (sum/count above T_hi; window -> g_h2 atomics)
//  D: last-finishing block scans g_h2, writes mean, re-zeroes all state
// ---------------------------------------------------------------------------
__global__ void __launch_bounds__(TPB, 2) kfused(const float* __restrict__ pred,
                                                 const float* __restrict__ tgt,
                                                 float* __restrict__ out) {
    __shared__ uint32_t sh[HBINS];           // 32 KB
    __shared__ uint32_t sscan[TPB];          // 4 KB
    __shared__ uint32_t s_last;
    __shared__ float    wp[32];
    __shared__ uint32_t wc[32];
    const int t = threadIdx.x;
    const uint32_t lane = t & 31u;

    // ===== Phase S: sampling =====
    for (int i = t; i < HBINS; i += TPB) sh[i] = 0u;
    __syncthreads();
    {
        int sidx = blockIdx.x * TPB + t;                 // first N_SAMP elements
        float l = bce_loss(pred[sidx], tgt[sidx]);
        atomicAdd(&sh[__float_as_uint(l) >> 18], 1u);
    }
    __syncthreads();
    for (int i = t; i < HBINS; i += TPB) {
        uint32_t c = sh[i];
        if (c) atomicAdd(&g_hist[i], c);
    }
    __threadfence();
    if (t == 0)
        s_last = (atomicAdd(&g_doneS, 1u) == (uint32_t)(GRID - 1)) ? 1u : 0u;
    __syncthreads();

    if (s_last) {
        // Descending-rank scan of g_hist -> T_lo, T_hi.
        uint4 h0 = ((const uint4*)g_hist)[t * 2];
        uint4 h1 = ((const uint4*)g_hist)[t * 2 + 1];
        uint32_t hb[8] = {h0.x, h0.y, h0.z, h0.w, h1.x, h1.y, h1.z, h1.w};
        uint32_t part = 0;
#pragma unroll
        for (int j = 0; j < 8; j++) part += hb[j];
        sscan[t] = part;
        __syncthreads();
        for (int off = 1; off < TPB; off <<= 1) {        // inclusive suffix scan
            uint32_t v = (t + off < TPB) ? sscan[t + off] : 0u;
            __syncthreads();
            sscan[t] += v;
            __syncthreads();
        }
        uint32_t tail = sscan[t] - part;                 // strictly-above count
        for (int j = 7; j >= 0; j--) {                   // bins high -> low
            uint32_t C = tail, h = hb[j];
            if (C < R_HI && C + h >= R_HI) g_Thi = ((uint32_t)(t * 8 + j) + 1u) << 18;
            if (C < R_LO && C + h >= R_LO) g_Tlo = ((uint32_t)(t * 8 + j)) << 18;
            tail += h;
        }
        __syncthreads();
        __threadfence();
        if (t == 0) atomicExch(&g_winReady, 1u);         // release window
    } else {
        if (t == 0) {                                    // all blocks resident ->
            while (atomicAdd(&g_winReady, 0u) == 0u)     // last sampler WILL arrive
                __nanosleep(64);
        }
        __syncthreads();
    }
    const uint32_t Tlo = *(volatile uint32_t*)&g_Tlo;
    const uint32_t Thi = *(volatile uint32_t*)&g_Thi;
    uint32_t pfx0; int s3; win_params(Tlo, Thi, pfx0, s3);

    // ===== Phase B: lean full streaming pass =====
    float fs = 0.0f;
    uint32_t ch = 0;
    int tid = blockIdx.x * TPB + t;
    const int stride = GRID * TPB;
    const float4* p4 = (const float4*)pred;
    const float4* t4 = (const float4*)tgt;

#define KM_PROC(PX, TX) do {                                               \
        uint32_t _v = __float_as_uint(bce_loss((PX), (TX)));               \
        if (_v >= Thi)      { fs += __uint_as_float(_v); ch++; }           \
        else if (_v >= Tlo) atomicAdd(&g_h2[(_v >> s3) & (H2BINS - 1)], 1u); \
    } while (0)

    for (int i = tid; i < N_VEC; i += 2 * stride) {      // 2x unroll for MLP
        float4 pa = p4[i], ta = t4[i];
        bool sec = (i + stride) < N_VEC;                 // warp-uniform
        float4 pb, tb;
        if (sec) { pb = p4[i + stride]; tb = t4[i + stride]; }
        KM_PROC(pa.x, ta.x); KM_PROC(pa.y, ta.y);
        KM_PROC(pa.z, ta.z); KM_PROC(pa.w, ta.w);
        if (sec) {
            KM_PROC(pb.x, tb.x); KM_PROC(pb.y, tb.y);
            KM_PROC(pb.z, tb.z); KM_PROC(pb.w, tb.w);
        }
    }
#undef KM_PROC

    // Block-reduce exact sum/count of v >= T_hi.
#pragma unroll
    for (int o = 16; o; o >>= 1) {
        fs += __shfl_down_sync(FULL, fs, o);
        ch += __shfl_down_sync(FULL, ch, o);
    }
    if (lane == 0) { wp[t >> 5] = fs; wc[t >> 5] = ch; }
    __syncthreads();
    if (t == 0) {
        double d = 0.0; uint32_t c = 0;
#pragma unroll
        for (int i = 0; i < 32; i++) { d += (double)wp[i]; c += wc[i]; }
        atomicAdd(&g_sum, d);
        atomicAdd(&g_cntAbove, c);
    }

    // ===== Phase D: last-finishing block finalizes =====
    __threadfence();                        // publish h2/sum/cnt
    __syncthreads();
    if (t == 0)
        s_last = (atomicAdd(&g_doneM, 1u) == (uint32_t)(GRID - 1)) ? 1u : 0u;
    __syncthreads();
    if (!s_last) return;

    __shared__ double   dp[32];
    __shared__ uint32_t s_B, s_need;
    const uint32_t kr = K_SEL - g_cntAbove;      // needed from the window

    uint4 h = ((const uint4*)g_h2)[t];           // coalesced: 4 bins/thread
    uint32_t hb[4] = {h.x, h.y, h.z, h.w};
    uint32_t part = hb[0] + hb[1] + hb[2] + hb[3];
    sscan[t] = part;
    __syncthreads();
    for (int off = 1; off < TPB; off <<= 1) {    // inclusive suffix scan
        uint32_t v = (t + off < TPB) ? sscan[t + off] : 0u;
        __syncthreads();
        sscan[t] += v;
        __syncthreads();
    }
    uint32_t tail = sscan[t] - part;             // count in chunks above t
    {
        uint32_t C = tail;
        for (int j = 3; j >= 0; j--) {           // bins high -> low
            uint32_t hh = hb[j];
            if (C < kr && C + hh >= kr) { s_B = (uint32_t)(t * 4 + j); s_need = kr - C; }
            C += hh;
        }
    }
    __syncthreads();
    const uint32_t B = s_B, need = s_need;

    // Contributions: full bins above B at midpoint, plus `need` elements at B.
    double ds = 0.0;
#pragma unroll
    for (int j = 0; j < 4; j++) {
        uint32_t idx = (uint32_t)(t * 4 + j);
        uint32_t hh = hb[j];
        if ((idx > B && hh) || idx == B) {
            uint32_t bits = (((pfx0 << 12) | idx) << s3) |
                            (s3 ? (1u << (s3 - 1)) : 0u);   // bin midpoint
            double m = (double)__uint_as_float(bits);
            ds += (idx > B) ? (double)hh * m : (double)need * m;
        }
    }
#pragma unroll
    for (int o = 16; o; o >>= 1) ds += __shfl_down_sync(FULL, ds, o);
    if (lane == 0) dp[t >> 5] = ds;
    __syncthreads();
    if (t == 0) {
        double tot = g_sum;
#pragma unroll
        for (int i = 0; i < 32; i++) tot += dp[i];
        out[0] = (float)(tot / (double)K_SEL);
    }
    __syncthreads();
    // Re-zero ALL state for the next graph replay (everyone else has exited;
    // their writes are visible via the g_doneM acquire chain).
    for (int i = t; i < HBINS; i += TPB) g_hist[i] = 0u;
    for (int i = t; i < H2BINS; i += TPB) g_h2[i] = 0u;
    if (t == 0) {
        g_sum = 0.0; g_cntAbove = 0u;
        g_doneS = 0u; g_doneM = 0u; g_winReady = 0u;
    }
}

// ---------------------------------------------------------------------------
extern "C" void kernel_launch(void* const* d_in, const int* in_sizes, int n_in,
                              void* d_out, int out_size) {
    (void)in_sizes; (void)n_in; (void)out_size;
    const float* pred = (const float*)d_in[0];
    const float* tgt  = (const float*)d_in[1];
    float* out = (float*)d_out;

    kfused<<<GRID, TPB>>>(pred, tgt, out);
}

// round 14
// speedup vs baseline: 1.0678x; 1.0678x over previous
#include <cuda_runtime.h>
#include <cuda_pipeline.h>
#include <stdint.h>

// Problem constants (SHAPE = (16,1,1024,1024), RATIO = 0.25)
#define N_TOTAL   16777216
#define N_VEC     (N_TOTAL / 4)
#define K_SEL     4194304u
#define FULL      0xFFFFFFFFu
#define HBINS     8192              // sample histogram bins = bits[30:18]
#define H2BINS    4096              // refinement histogram: window bits [b:b-11]
#define S_TPB     1024
#define S_BLOCKS  128               // 128*1024 = 131072 samples
#define R_HI      30848u            // sample-rank (from top) for T_hi (K_s - 12sigma)
#define R_LO      34688u            // sample-rank for T_lo (K_s + 12sigma)
#define M_GRID    296               // 2 CTAs x 148 SMs
#define M_TPB     512

// Device-global state (statically zero-initialized)
__device__ __align__(16) uint32_t g_hist[HBINS];
__device__ __align__(16) uint32_t g_h2[H2BINS];
__device__ uint32_t g_Tlo, g_Thi;
__device__ uint32_t g_cntAbove;                  // # elements >= T_hi
__device__ double   g_sum;                       // exact sum of elements >= T_hi
__device__ uint32_t g_doneS, g_doneM;            // completion counters

// ---------------------------------------------------------------------------
__device__ __forceinline__ float bce_loss(float x, float t) {
    // max(x,0) - x*t + log1p(exp(-|x|)); always >= 0 for t in [0,1)
    float e = __expf(-fabsf(x));
    float base = fmaf(-x, t, fmaxf(x, 0.0f));
    float l = base + __logf(1.0f + e);
    return fmaxf(l, 0.0f);   // keep sign bit 0 -> uint order == float order
}

// b = highest bit where window values can differ (clamped >= 11).
// All window v share bits [31:b+1] == pfx0; histogram indexes bits [b:b-11].
__device__ __forceinline__ void win_params(uint32_t Tlo, uint32_t Thi,
                                           uint32_t& pfx0, int& s3) {
    uint32_t m = Tlo ^ (Thi - 1u);
    int b = m ? (31 - __clz((int)m)) : 11;
    if (b < 11) b = 11;
    s3 = b - 11;                       // bin width = 2^s3 ulps
    pfx0 = Tlo >> (b + 1);
}

// ---------------------------------------------------------------------------
// ksample: zero g_h2; BCE on first 131072 elements -> 8192-bin coarse
// histogram; LAST block derives [T_lo,T_hi), publishes it, resets g_hist.
// (Unchanged from the rel_err=0.0 configuration.)
// ---------------------------------------------------------------------------
__global__ void __launch_bounds__(S_TPB) ksample(const float* __restrict__ pred,
                                                 const float* __restrict__ tgt) {
    __shared__ uint32_t sh[HBINS];
    __shared__ uint32_t sscan[S_TPB];
    __shared__ uint32_t s_last;
    const int t = threadIdx.x;
    int gidx = blockIdx.x * S_TPB + t;
    if (gidx < H2BINS) g_h2[gidx] = 0u;            // 128K threads >= 4K bins
    for (int i = t; i < HBINS; i += S_TPB) sh[i] = 0u;
    __syncthreads();

    float l = bce_loss(pred[gidx], tgt[gidx]);     // one sample per thread
    atomicAdd(&sh[__float_as_uint(l) >> 18], 1u);
    __syncthreads();
    for (int i = t; i < HBINS; i += S_TPB) {
        uint32_t c = sh[i];
        if (c) atomicAdd(&g_hist[i], c);
    }
    __threadfence();
    if (t == 0)
        s_last = (atomicAdd(&g_doneS, 1u) == (uint32_t)(S_BLOCKS - 1)) ? 1u : 0u;
    __syncthreads();
    if (!s_last) return;

    // Last block: descending-rank scan of g_hist -> T_lo, T_hi.
    uint4 h0 = ((const uint4*)g_hist)[t * 2];
    uint4 h1 = ((const uint4*)g_hist)[t * 2 + 1];
    uint32_t hb[8] = {h0.x, h0.y, h0.z, h0.w, h1.x, h1.y, h1.z, h1.w};
    uint32_t part = 0;
#pragma unroll
    for (int j = 0; j < 8; j++) part += hb[j];
    sscan[t] = part;
    __syncthreads();
    for (int off = 1; off < S_TPB; off <<= 1) {     // inclusive suffix scan
        uint32_t v = (t + off < S_TPB) ? sscan[t + off] : 0u;
        __syncthreads();
        sscan[t] += v;
        __syncthreads();
    }
    uint32_t tail = sscan[t] - part;                // strictly-above count
    for (int j = 7; j >= 0; j--) {                  // bins high -> low
        uint32_t C = tail, h = hb[j];
        if (C < R_HI && C + h >= R_HI) g_Thi = ((uint32_t)(t * 8 + j) + 1u) << 18;
        if (C < R_LO && C + h >= R_LO) g_Tlo = ((uint32_t)(t * 8 + j)) << 18;
        tail += h;
    }
    // Reset state consumed this replay.
    for (int i = t; i < HBINS; i += S_TPB) g_hist[i] = 0u;
    if (t == 0) g_doneS = 0u;
}

// ---------------------------------------------------------------------------
// kmain: full pass with cp.async double-buffering. Each thread prefetches its
// NEXT float4 of pred/tgt into its private smem slot (no scoreboard bind, no
// block syncs in the hot loop), computes on the CURRENT buffer:
//   v >= T_hi        -> register sum + count
//   T_lo <= v < T_hi -> predicated atomicAdd into 4096-bin g_h2
// LAST finishing block: coalesced scan of g_h2, mean, write out, reset state.
// ---------------------------------------------------------------------------
__global__ void __launch_bounds__(M_TPB, 2) kmain(const float* __restrict__ pred,
                                                  const float* __restrict__ tgt,
                                                  float* __restrict__ out) {
    __shared__ float4 sp[2][M_TPB];      // 16 KB
    __shared__ float4 st[2][M_TPB];      // 16 KB
    __shared__ float    wp[16];
    __shared__ uint32_t wc[16];
    __shared__ uint32_t s_last;
    const int t = threadIdx.x;
    const uint32_t lane = t & 31u;
    const uint32_t Tlo = g_Tlo, Thi = g_Thi;       // scalars, L2-broadcast
    uint32_t pfx0; int s3; win_params(Tlo, Thi, pfx0, s3);

    const float4* p4 = (const float4*)pred;
    const float4* t4 = (const float4*)tgt;
    const int tid0   = blockIdx.x * M_TPB + t;
    const int stride = M_GRID * M_TPB;

    float fs = 0.0f;
    uint32_t ch = 0;

#define KM_PROC(PX, TX) do {                                               \
        uint32_t _v = __float_as_uint(bce_loss((PX), (TX)));               \
        if (_v >= Thi)      { fs += __uint_as_float(_v); ch++; }           \
        else if (_v >= Tlo) atomicAdd(&g_h2[(_v >> s3) & (H2BINS - 1)], 1u); \
    } while (0)

    if (tid0 < N_VEC) {
        // Prologue: prefetch iteration 0 (group g0).
        __pipeline_memcpy_async(&sp[0][t], &p4[tid0], 16);
        __pipeline_memcpy_async(&st[0][t], &t4[tid0], 16);
        __pipeline_commit();

        int buf = 0;
        for (int i = tid0; i < N_VEC; i += stride) {
            int inext = i + stride;
            int ipf = (inext < N_VEC) ? inext : i;      // clamped prefetch
            __pipeline_memcpy_async(&sp[buf ^ 1][t], &p4[ipf], 16);
            __pipeline_memcpy_async(&st[buf ^ 1][t], &t4[ipf], 16);
            __pipeline_commit();
            __pipeline_wait_prior(1);                   // current buffer ready
            float4 pa = sp[buf][t];
            float4 ta = st[buf][t];
            KM_PROC(pa.x, ta.x); KM_PROC(pa.y, ta.y);
            KM_PROC(pa.z, ta.z); KM_PROC(pa.w, ta.w);
            buf ^= 1;
        }
        __pipeline_wait_prior(0);                       // drain tail prefetch
    }
#undef KM_PROC

    // Block-reduce exact sum/count of v >= T_hi.
#pragma unroll
    for (int o = 16; o; o >>= 1) {
        fs += __shfl_down_sync(FULL, fs, o);
        ch += __shfl_down_sync(FULL, ch, o);
    }
    if (lane == 0) { wp[t >> 5] = fs; wc[t >> 5] = ch; }
    __syncthreads();
    if (t == 0) {
        double d = 0.0; uint32_t c = 0;
#pragma unroll
        for (int i = 0; i < 16; i++) { d += (double)wp[i]; c += wc[i]; }
        atomicAdd(&g_sum, d);
        atomicAdd(&g_cntAbove, c);
    }

    // --- Last-finishing block finalizes ---
    __threadfence();                       // publish h2/sum/cnt
    __syncthreads();
    if (t == 0)
        s_last = (atomicAdd(&g_doneM, 1u) == (uint32_t)(M_GRID - 1)) ? 1u : 0u;
    __syncthreads();
    if (!s_last) return;

    // Reuse streaming smem as scan storage (all threads past streaming).
    uint32_t* sscan = (uint32_t*)&sp[0][0];
    __shared__ double   dp[16];
    __shared__ uint32_t s_B, s_need;
    const uint32_t kr = K_SEL - g_cntAbove;     // needed from the window

    // 8 bins per thread, coalesced uint4 pairs.
    uint4 h0 = ((const uint4*)g_h2)[t * 2];
    uint4 h1 = ((const uint4*)g_h2)[t * 2 + 1];
    uint32_t hb[8] = {h0.x, h0.y, h0.z, h0.w, h1.x, h1.y, h1.z, h1.w};
    uint32_t part = 0;
#pragma unroll
    for (int j = 0; j < 8; j++) part += hb[j];
    sscan[t] = part;
    __syncthreads();
    for (int off = 1; off < M_TPB; off <<= 1) {  // inclusive suffix scan
        uint32_t v = (t + off < M_TPB) ? sscan[t + off] : 0u;
        __syncthreads();
        sscan[t] += v;
        __syncthreads();
    }
    uint32_t tail = sscan[t] - part;             // count in chunks above t
    {
        uint32_t C = tail;
        for (int j = 7; j >= 0; j--) {           // bins high -> low
            uint32_t hh = hb[j];
            if (C < kr && C + hh >= kr) { s_B = (uint32_t)(t * 8 + j); s_need = kr - C; }
            C += hh;
        }
    }
    __syncthreads();
    const uint32_t B = s_B, need = s_need;

    // Contributions: full bins above B at midpoint, plus `need` elements at B.
    double ds = 0.0;
#pragma unroll
    for (int j = 0; j < 8; j++) {
        uint32_t idx = (uint32_t)(t * 8 + j);
        uint32_t hh = hb[j];
        if ((idx > B && hh) || idx == B) {
            uint32_t bits = (((pfx0 << 12) | idx) << s3) |
                            (s3 ? (1u << (s3 - 1)) : 0u);   // bin midpoint
            double m = (double)__uint_as_float(bits);
            ds += (idx > B) ? (double)hh * m : (double)need * m;
        }
    }
#pragma unroll
    for (int o = 16; o; o >>= 1) ds += __shfl_down_sync(FULL, ds, o);
    if (lane == 0) dp[t >> 5] = ds;
    __syncthreads();
    if (t == 0) {
        double tot = g_sum;
#pragma unroll
        for (int i = 0; i < 16; i++) tot += dp[i];
        out[0] = (float)(tot / (double)K_SEL);
    }
    __syncthreads();
    // Re-zero scalars for next replay (g_h2/g_hist re-zeroed by next ksample).
    if (t == 0) { g_sum = 0.0; g_cntAbove = 0u; g_doneM = 0u; }
}

// ---------------------------------------------------------------------------
extern "C" void kernel_launch(void* const* d_in, const int* in_sizes, int n_in,
                              void* d_out, int out_size) {
    (void)in_sizes; (void)n_in; (void)out_size;
    const float* pred = (const float*)d_in[0];
    const float* tgt  = (const float*)d_in[1];
    float* out = (float*)d_out;

    ksample<<<S_BLOCKS, S_TPB>>>(pred, tgt);
    kmain<<<M_GRID, M_TPB>>>(pred, tgt, out);
}

// round 15
// speedup vs baseline: 1.0708x; 1.0028x over previous
#include <cuda_runtime.h>
#include <cuda_pipeline.h>
#include <stdint.h>

// Problem constants (SHAPE = (16,1,1024,1024), RATIO = 0.25)
#define N_TOTAL   16777216
#define N_VEC     (N_TOTAL / 4)
#define K_SEL     4194304u
#define FULL      0xFFFFFFFFu
#define HBINS     8192              // sample histogram bins = bits[30:18]
#define H2BINS    4096              // refinement histogram: window bits [b:b-11]
#define S_TPB     1024
#define S_BLOCKS  128               // 128*1024 = 131072 samples
#define R_HI      30848u            // sample-rank (from top) for T_hi (K_s - 12sigma)
#define R_LO      34688u            // sample-rank for T_lo (K_s + 12sigma)
#define M_GRID    296               // 2 CTAs x 148 SMs
#define M_TPB     512
#define STAGES    4

// Device-global state (statically zero-initialized)
__device__ __align__(16) uint32_t g_hist[HBINS];
__device__ __align__(16) uint32_t g_h2[H2BINS];
__device__ uint32_t g_Tlo, g_Thi;
__device__ uint32_t g_cntAbove;                  // # elements >= T_hi
__device__ double   g_sum;                       // exact sum of elements >= T_hi
__device__ uint32_t g_doneS, g_doneM;            // completion counters

// ---------------------------------------------------------------------------
__device__ __forceinline__ float bce_loss(float x, float t) {
    // max(x,0) - x*t + log1p(exp(-|x|)); always >= 0 for t in [0,1)
    float e = __expf(-fabsf(x));
    float base = fmaf(-x, t, fmaxf(x, 0.0f));
    float l = base + __logf(1.0f + e);
    return fmaxf(l, 0.0f);   // keep sign bit 0 -> uint order == float order
}

// b = highest bit where window values can differ (clamped >= 11).
// All window v share bits [31:b+1] == pfx0; histogram indexes bits [b:b-11].
__device__ __forceinline__ void win_params(uint32_t Tlo, uint32_t Thi,
                                           uint32_t& pfx0, int& s3) {
    uint32_t m = Tlo ^ (Thi - 1u);
    int b = m ? (31 - __clz((int)m)) : 11;
    if (b < 11) b = 11;
    s3 = b - 11;                       // bin width = 2^s3 ulps
    pfx0 = Tlo >> (b + 1);
}

// ---------------------------------------------------------------------------
// ksample: zero g_h2; BCE on first 131072 elements -> 8192-bin coarse
// histogram; LAST block derives [T_lo,T_hi), publishes it, resets g_hist.
// ---------------------------------------------------------------------------
__global__ void __launch_bounds__(S_TPB) ksample(const float* __restrict__ pred,
                                                 const float* __restrict__ tgt) {
    __shared__ uint32_t sh[HBINS];
    __shared__ uint32_t sscan[S_TPB];
    __shared__ uint32_t s_last;
    const int t = threadIdx.x;
    int gidx = blockIdx.x * S_TPB + t;
    if (gidx < H2BINS) g_h2[gidx] = 0u;            // 128K threads >= 4K bins
    for (int i = t; i < HBINS; i += S_TPB) sh[i] = 0u;
    __syncthreads();

    float l = bce_loss(pred[gidx], tgt[gidx]);     // one sample per thread
    atomicAdd(&sh[__float_as_uint(l) >> 18], 1u);
    __syncthreads();
    for (int i = t; i < HBINS; i += S_TPB) {
        uint32_t c = sh[i];
        if (c) atomicAdd(&g_hist[i], c);
    }
    __threadfence();
    if (t == 0)
        s_last = (atomicAdd(&g_doneS, 1u) == (uint32_t)(S_BLOCKS - 1)) ? 1u : 0u;
    __syncthreads();
    if (!s_last) return;

    // Last block: descending-rank scan of g_hist -> T_lo, T_hi.
    uint4 h0 = ((const uint4*)g_hist)[t * 2];
    uint4 h1 = ((const uint4*)g_hist)[t * 2 + 1];
    uint32_t hb[8] = {h0.x, h0.y, h0.z, h0.w, h1.x, h1.y, h1.z, h1.w};
    uint32_t part = 0;
#pragma unroll
    for (int j = 0; j < 8; j++) part += hb[j];
    sscan[t] = part;
    __syncthreads();
    for (int off = 1; off < S_TPB; off <<= 1) {     // inclusive suffix scan
        uint32_t v = (t + off < S_TPB) ? sscan[t + off] : 0u;
        __syncthreads();
        sscan[t] += v;
        __syncthreads();
    }
    uint32_t tail = sscan[t] - part;                // strictly-above count
    for (int j = 7; j >= 0; j--) {                  // bins high -> low
        uint32_t C = tail, h = hb[j];
        if (C < R_HI && C + h >= R_HI) g_Thi = ((uint32_t)(t * 8 + j) + 1u) << 18;
        if (C < R_LO && C + h >= R_LO) g_Tlo = ((uint32_t)(t * 8 + j)) << 18;
        tail += h;
    }
    // Reset state consumed this replay.
    for (int i = t; i < HBINS; i += S_TPB) g_hist[i] = 0u;
    if (t == 0) g_doneS = 0u;
}

// ---------------------------------------------------------------------------
// kmain: full pass, 4-stage cp.async ring buffer (prefetch distance 3; no
// block syncs in the hot loop — each thread consumes only its own slots):
//   v >= T_hi        -> register sum + count
//   T_lo <= v < T_hi -> predicated atomicAdd into 4096-bin g_h2
// LAST finishing block: coalesced scan of g_h2, mean, write out, reset state.
// ---------------------------------------------------------------------------
__global__ void __launch_bounds__(M_TPB, 2) kmain(const float* __restrict__ pred,
                                                  const float* __restrict__ tgt,
                                                  float* __restrict__ out) {
    __shared__ float4 sp[STAGES][M_TPB];     // 32 KB
    __shared__ float4 st[STAGES][M_TPB];     // 32 KB
    __shared__ float    wp[16];
    __shared__ uint32_t wc[16];
    __shared__ uint32_t s_last;
    const int t = threadIdx.x;
    const uint32_t lane = t & 31u;
    const uint32_t Tlo = g_Tlo, Thi = g_Thi;       // scalars, L2-broadcast
    uint32_t pfx0; int s3; win_params(Tlo, Thi, pfx0, s3);

    const float4* p4 = (const float4*)pred;
    const float4* t4 = (const float4*)tgt;
    const int tid0   = blockIdx.x * M_TPB + t;
    const int stride = M_GRID * M_TPB;

    float fs = 0.0f;
    uint32_t ch = 0;

#define KM_PROC(PX, TX) do {                                               \
        uint32_t _v = __float_as_uint(bce_loss((PX), (TX)));               \
        if (_v >= Thi)      { fs += __uint_as_float(_v); ch++; }           \
        else if (_v >= Tlo) atomicAdd(&g_h2[(_v >> s3) & (H2BINS - 1)], 1u); \
    } while (0)

    // Prologue: prefetch stages 0..2 (indices tid0, +stride, +2*stride — all
    // guaranteed < N_VEC since 3*stride = 454656 << N_VEC).
#pragma unroll
    for (int s = 0; s < STAGES - 1; s++) {
        __pipeline_memcpy_async(&sp[s][t], &p4[tid0 + s * stride], 16);
        __pipeline_memcpy_async(&st[s][t], &t4[tid0 + s * stride], 16);
        __pipeline_commit();
    }

    int buf = 0;
    for (int i = tid0; i < N_VEC; i += stride) {     // warp-uniform trip count
        int ipf = i + (STAGES - 1) * stride;
        int ipfc = (ipf < N_VEC) ? ipf : i;          // clamped dummy prefetch
        int pfslot = (buf + STAGES - 1) & (STAGES - 1);
        __pipeline_memcpy_async(&sp[pfslot][t], &p4[ipfc], 16);
        __pipeline_memcpy_async(&st[pfslot][t], &t4[ipfc], 16);
        __pipeline_commit();
        __pipeline_wait_prior(STAGES - 1);           // stage `buf` is ready
        float4 pa = sp[buf][t];
        float4 ta = st[buf][t];
        KM_PROC(pa.x, ta.x); KM_PROC(pa.y, ta.y);
        KM_PROC(pa.z, ta.z); KM_PROC(pa.w, ta.w);
        buf = (buf + 1) & (STAGES - 1);
    }
    __pipeline_wait_prior(0);                        // drain tail prefetches
#undef KM_PROC

    // Block-reduce exact sum/count of v >= T_hi.
#pragma unroll
    for (int o = 16; o; o >>= 1) {
        fs += __shfl_down_sync(FULL, fs, o);
        ch += __shfl_down_sync(FULL, ch, o);
    }
    if (lane == 0) { wp[t >> 5] = fs; wc[t >> 5] = ch; }
    __syncthreads();
    if (t == 0) {
        double d = 0.0; uint32_t c = 0;
#pragma unroll
        for (int i = 0; i < 16; i++) { d += (double)wp[i]; c += wc[i]; }
        atomicAdd(&g_sum, d);
        atomicAdd(&g_cntAbove, c);
    }

    // --- Last-finishing block finalizes ---
    __threadfence();                       // publish h2/sum/cnt
    __syncthreads();
    if (t == 0)
        s_last = (atomicAdd(&g_doneM, 1u) == (uint32_t)(M_GRID - 1)) ? 1u : 0u;
    __syncthreads();
    if (!s_last) return;

    // Reuse streaming smem as scan storage (all threads past streaming).
    uint32_t* sscan = (uint32_t*)&sp[0][0];
    __shared__ double   dp[16];
    __shared__ uint32_t s_B, s_need;
    const uint32_t kr = K_SEL - g_cntAbove;     // needed from the window

    // 8 bins per thread, coalesced uint4 pairs.
    uint4 h0 = ((const uint4*)g_h2)[t * 2];
    uint4 h1 = ((const uint4*)g_h2)[t * 2 + 1];
    uint32_t hb[8] = {h0.x, h0.y, h0.z, h0.w, h1.x, h1.y, h1.z, h1.w};
    uint32_t part = 0;
#pragma unroll
    for (int j = 0; j < 8; j++) part += hb[j];
    sscan[t] = part;
    __syncthreads();
    for (int off = 1; off < M_TPB; off <<= 1) {  // inclusive suffix scan
        uint32_t v = (t + off < M_TPB) ? sscan[t + off] : 0u;
        __syncthreads();
        sscan[t] += v;
        __syncthreads();
    }
    uint32_t tail = sscan[t] - part;             // count in chunks above t
    {
        uint32_t C = tail;
        for (int j = 7; j >= 0; j--) {           // bins high -> low
            uint32_t hh = hb[j];
            if (C < kr && C + hh >= kr) { s_B = (uint32_t)(t * 8 + j); s_need = kr - C; }
            C += hh;
        }
    }
    __syncthreads();
    const uint32_t B = s_B, need = s_need;

    // Contributions: full bins above B at midpoint, plus `need` elements at B.
    double ds = 0.0;
#pragma unroll
    for (int j = 0; j < 8; j++) {
        uint32_t idx = (uint32_t)(t * 8 + j);
        uint32_t hh = hb[j];
        if ((idx > B && hh) || idx == B) {
            uint32_t bits = (((pfx0 << 12) | idx) << s3) |
                            (s3 ? (1u << (s3 - 1)) : 0u);   // bin midpoint
            double m = (double)__uint_as_float(bits);
            ds += (idx > B) ? (double)hh * m : (double)need * m;
        }
    }
#pragma unroll
    for (int o = 16; o; o >>= 1) ds += __shfl_down_sync(FULL, ds, o);
    if (lane == 0) dp[t >> 5] = ds;
    __syncthreads();
    if (t == 0) {
        double tot = g_sum;
#pragma unroll
        for (int i = 0; i < 16; i++) tot += dp[i];
        out[0] = (float)(tot / (double)K_SEL);
    }
    __syncthreads();
    // Re-zero scalars for next replay (g_h2/g_hist re-zeroed by next ksample).
    if (t == 0) { g_sum = 0.0; g_cntAbove = 0u; g_doneM = 0u; }
}

// ---------------------------------------------------------------------------
extern "C" void kernel_launch(void* const* d_in, const int* in_sizes, int n_in,
                              void* d_out, int out_size) {
    (void)in_sizes; (void)n_in; (void)out_size;
    const float* pred = (const float*)d_in[0];
    const float* tgt  = (const float*)d_in[1];
    float* out = (float*)d_out;

    ksample<<<S_BLOCKS, S_TPB>>>(pred, tgt);
    kmain<<<M_GRID, M_TPB>>>(pred, tgt, out);
}

// round 16
// speedup vs baseline: 1.0768x; 1.0056x over previous
#include <cuda_runtime.h>
#include <stdint.h>

// Problem constants (SHAPE = (16,1,1024,1024), RATIO = 0.25)
#define N_TOTAL   16777216
#define N_VEC     (N_TOTAL / 4)
#define K_SEL     4194304u
#define FULL      0xFFFFFFFFu
#define HBINS     8192              // sample histogram bins = bits[30:18]
#define H2BINS    4096              // refinement histogram: window bits [b:b-11]
#define S_TPB     1024
#define S_BLOCKS  128               // 128*1024 = 131072 samples
#define R_HI      30848u            // sample-rank (from top) for T_hi (K_s - 12sigma)
#define R_LO      34688u            // sample-rank for T_lo (K_s + 12sigma)
#define M_GRID    296               // 2 CTAs x 148 SMs
#define M_TPB     512
#define T_ELEM    4096              // floats per array per tile (16 KB)
#define TILE_BYTES (T_ELEM * 4)
#define NTILES    (N_TOTAL / T_ELEM)     // 4096 tiles, exact
#define STAGES    3
#define SMEM_DYN  (2 * STAGES * TILE_BYTES + 64)   // tiles + mbarriers

// Device-global state (statically zero-initialized)
__device__ __align__(16) uint32_t g_hist[HBINS];
__device__ __align__(16) uint32_t g_h2[H2BINS];
__device__ uint32_t g_Tlo, g_Thi;
__device__ uint32_t g_cntAbove;                  // # elements >= T_hi
__device__ double   g_sum;                       // exact sum of elements >= T_hi
__device__ uint32_t g_doneS, g_doneM;            // completion counters

// ---------------------------------------------------------------------------
__device__ __forceinline__ float bce_loss(float x, float t) {
    // max(x,0) - x*t + log1p(exp(-|x|)); always >= 0 for t in [0,1)
    float e = __expf(-fabsf(x));
    float base = fmaf(-x, t, fmaxf(x, 0.0f));
    float l = base + __logf(1.0f + e);
    return fmaxf(l, 0.0f);   // keep sign bit 0 -> uint order == float order
}

__device__ __forceinline__ void win_params(uint32_t Tlo, uint32_t Thi,
                                           uint32_t& pfx0, int& s3) {
    uint32_t m = Tlo ^ (Thi - 1u);
    int b = m ? (31 - __clz((int)m)) : 11;
    if (b < 11) b = 11;
    s3 = b - 11;                       // bin width = 2^s3 ulps
    pfx0 = Tlo >> (b + 1);
}

// ---- TMA / mbarrier helpers (raw PTX; sm_90+) -----------------------------
__device__ __forceinline__ void mbar_init(uint32_t a, uint32_t cnt) {
    asm volatile("mbarrier.init.shared.b64 [%0], %1;" :: "r"(a), "r"(cnt) : "memory");
}
__device__ __forceinline__ void mbar_expect(uint32_t a, uint32_t bytes) {
    asm volatile("mbarrier.arrive.expect_tx.shared.b64 _, [%0], %1;"
                 :: "r"(a), "r"(bytes) : "memory");
}
__device__ __forceinline__ void bulk_g2s(uint32_t dst, const void* src,
                                         uint32_t bytes, uint32_t mbar) {
    asm volatile(
        "cp.async.bulk.shared::cta.global.mbarrier::complete_tx::bytes "
        "[%0], [%1], %2, [%3];"
        :: "r"(dst), "l"(src), "r"(bytes), "r"(mbar) : "memory");
}
__device__ __forceinline__ void mbar_wait(uint32_t a, uint32_t ph) {
    asm volatile(
        "{\n\t.reg .pred P;\n"
        "W_%=:\n\t"
        "mbarrier.try_wait.parity.acquire.cta.shared::cta.b64 P, [%0], %1, 0x989680;\n\t"
        "@!P bra W_%=;\n\t"
        "}" :: "r"(a), "r"(ph) : "memory");
}

// ---------------------------------------------------------------------------
// ksample: zero g_h2; BCE on first 131072 elements -> 8192-bin coarse
// histogram; LAST block derives [T_lo,T_hi), publishes it, resets g_hist.
// (Unchanged from the rel_err = 0.0 configuration.)
// ---------------------------------------------------------------------------
__global__ void __launch_bounds__(S_TPB) ksample(const float* __restrict__ pred,
                                                 const float* __restrict__ tgt) {
    __shared__ uint32_t sh[HBINS];
    __shared__ uint32_t sscan[S_TPB];
    __shared__ uint32_t s_last;
    const int t = threadIdx.x;
    int gidx = blockIdx.x * S_TPB + t;
    if (gidx < H2BINS) g_h2[gidx] = 0u;
    for (int i = t; i < HBINS; i += S_TPB) sh[i] = 0u;
    __syncthreads();

    float l = bce_loss(pred[gidx], tgt[gidx]);
    atomicAdd(&sh[__float_as_uint(l) >> 18], 1u);
    __syncthreads();
    for (int i = t; i < HBINS; i += S_TPB) {
        uint32_t c = sh[i];
        if (c) atomicAdd(&g_hist[i], c);
    }
    __threadfence();
    if (t == 0)
        s_last = (atomicAdd(&g_doneS, 1u) == (uint32_t)(S_BLOCKS - 1)) ? 1u : 0u;
    __syncthreads();
    if (!s_last) return;

    uint4 h0 = ((const uint4*)g_hist)[t * 2];
    uint4 h1 = ((const uint4*)g_hist)[t * 2 + 1];
    uint32_t hb[8] = {h0.x, h0.y, h0.z, h0.w, h1.x, h1.y, h1.z, h1.w};
    uint32_t part = 0;
#pragma unroll
    for (int j = 0; j < 8; j++) part += hb[j];
    sscan[t] = part;
    __syncthreads();
    for (int off = 1; off < S_TPB; off <<= 1) {
        uint32_t v = (t + off < S_TPB) ? sscan[t + off] : 0u;
        __syncthreads();
        sscan[t] += v;
        __syncthreads();
    }
    uint32_t tail = sscan[t] - part;
    for (int j = 7; j >= 0; j--) {
        uint32_t C = tail, h = hb[j];
        if (C < R_HI && C + h >= R_HI) g_Thi = ((uint32_t)(t * 8 + j) + 1u) << 18;
        if (C < R_LO && C + h >= R_LO) g_Tlo = ((uint32_t)(t * 8 + j)) << 18;
        tail += h;
    }
    for (int i = t; i < HBINS; i += S_TPB) g_hist[i] = 0u;
    if (t == 0) g_doneS = 0u;
}

// ---------------------------------------------------------------------------
// kmain: TMA-bulk tile pipeline (3 stages x 32 KB). Thread 0 issues bulk
// copies; block waits on mbarrier parity; registers loaded, stage re-armed,
// then compute:
//   v >= T_hi        -> register sum + count
//   T_lo <= v < T_hi -> predicated atomicAdd into 4096-bin g_h2
// LAST finishing block: coalesced scan of g_h2, mean, write out, reset state.
// ---------------------------------------------------------------------------
__global__ void __launch_bounds__(M_TPB, 2) kmain(const float* __restrict__ pred,
                                                  const float* __restrict__ tgt,
                                                  float* __restrict__ out) {
    extern __shared__ __align__(16) char dsm[];
    float* sp = (float*)dsm;                          // [STAGES][T_ELEM] pred
    float* st = sp + STAGES * T_ELEM;                 // [STAGES][T_ELEM] tgt
    __shared__ float    wp[16];
    __shared__ uint32_t wc[16];
    __shared__ uint32_t s_last;
    const int t = threadIdx.x;
    const uint32_t lane = t & 31u;
    const uint32_t Tlo = g_Tlo, Thi = g_Thi;
    uint32_t pfx0; int s3; win_params(Tlo, Thi, pfx0, s3);

    const uint32_t sp_base = (uint32_t)__cvta_generic_to_shared(sp);
    const uint32_t st_base = (uint32_t)__cvta_generic_to_shared(st);
    const uint32_t mb_base = (uint32_t)__cvta_generic_to_shared(st + STAGES * T_ELEM);

    if (t == 0)
        for (int s = 0; s < STAGES; s++) mbar_init(mb_base + 8 * s, 1u);
    __syncthreads();

    const int bid = blockIdx.x;
    const int nt = (NTILES - 1 - bid) / M_GRID + 1;   // tiles for this CTA

    // Prologue: fill up to STAGES stages.
    if (t == 0) {
        int pe = nt < STAGES ? nt : STAGES;
        for (int s = 0; s < pe; s++) {
            size_t g = (size_t)(bid + s * M_GRID) * T_ELEM;
            mbar_expect(mb_base + 8 * s, 2 * TILE_BYTES);
            bulk_g2s(sp_base + s * TILE_BYTES, pred + g, TILE_BYTES, mb_base + 8 * s);
            bulk_g2s(st_base + s * TILE_BYTES, tgt  + g, TILE_BYTES, mb_base + 8 * s);
        }
    }

    float fs = 0.0f;
    uint32_t ch = 0;

#define KM_PROC(PX, TX) do {                                               \
        uint32_t _v = __float_as_uint(bce_loss((PX), (TX)));               \
        if (_v >= Thi)      { fs += __uint_as_float(_v); ch++; }           \
        else if (_v >= Tlo) atomicAdd(&g_h2[(_v >> s3) & (H2BINS - 1)], 1u); \
    } while (0)

    for (int lt = 0; lt < nt; lt++) {
        int s = lt % STAGES;
        uint32_t ph = (uint32_t)(lt / STAGES) & 1u;
        mbar_wait(mb_base + 8 * s, ph);
        const float4* sp4 = (const float4*)(sp + s * T_ELEM);
        const float4* st4 = (const float4*)(st + s * T_ELEM);
        float4 pa = sp4[t], pb = sp4[t + M_TPB];
        float4 ta = st4[t], tb = st4[t + M_TPB];
        __syncthreads();                              // all regs loaded
        if (t == 0 && lt + STAGES < nt) {             // re-arm this stage
            size_t g = (size_t)(bid + (lt + STAGES) * M_GRID) * T_ELEM;
            mbar_expect(mb_base + 8 * s, 2 * TILE_BYTES);
            bulk_g2s(sp_base + s * TILE_BYTES, pred + g, TILE_BYTES, mb_base + 8 * s);
            bulk_g2s(st_base + s * TILE_BYTES, tgt  + g, TILE_BYTES, mb_base + 8 * s);
        }
        KM_PROC(pa.x, ta.x); KM_PROC(pa.y, ta.y);
        KM_PROC(pa.z, ta.z); KM_PROC(pa.w, ta.w);
        KM_PROC(pb.x, tb.x); KM_PROC(pb.y, tb.y);
        KM_PROC(pb.z, tb.z); KM_PROC(pb.w, tb.w);
    }
#undef KM_PROC

    // Block-reduce exact sum/count of v >= T_hi.
#pragma unroll
    for (int o = 16; o; o >>= 1) {
        fs += __shfl_down_sync(FULL, fs, o);
        ch += __shfl_down_sync(FULL, ch, o);
    }
    if (lane == 0) { wp[t >> 5] = fs; wc[t >> 5] = ch; }
    __syncthreads();
    if (t == 0) {
        double d = 0.0; uint32_t c = 0;
#pragma unroll
        for (int i = 0; i < 16; i++) { d += (double)wp[i]; c += wc[i]; }
        atomicAdd(&g_sum, d);
        atomicAdd(&g_cntAbove, c);
    }

    // --- Last-finishing block finalizes ---
    __threadfence();
    __syncthreads();
    if (t == 0)
        s_last = (atomicAdd(&g_doneM, 1u) == (uint32_t)(M_GRID - 1)) ? 1u : 0u;
    __syncthreads();
    if (!s_last) return;

    uint32_t* sscan = (uint32_t*)dsm;          // reuse tile smem
    __shared__ double   dp[16];
    __shared__ uint32_t s_B, s_need;
    const uint32_t kr = K_SEL - g_cntAbove;

    uint4 h0 = ((const uint4*)g_h2)[t * 2];
    uint4 h1 = ((const uint4*)g_h2)[t * 2 + 1];
    uint32_t hb[8] = {h0.x, h0.y, h0.z, h0.w, h1.x, h1.y, h1.z, h1.w};
    uint32_t part = 0;
#pragma unroll
    for (int j = 0; j < 8; j++) part += hb[j];
    sscan[t] = part;
    __syncthreads();
    for (int off = 1; off < M_TPB; off <<= 1) {
        uint32_t v = (t + off < M_TPB) ? sscan[t + off] : 0u;
        __syncthreads();
        sscan[t] += v;
        __syncthreads();
    }
    uint32_t tail = sscan[t] - part;
    {
        uint32_t C = tail;
        for (int j = 7; j >= 0; j--) {
            uint32_t hh = hb[j];
            if (C < kr && C + hh >= kr) { s_B = (uint32_t)(t * 8 + j); s_need = kr - C; }
            C += hh;
        }
    }
    __syncthreads();
    const uint32_t B = s_B, need = s_need;

    double ds = 0.0;
#pragma unroll
    for (int j = 0; j < 8; j++) {
        uint32_t idx = (uint32_t)(t * 8 + j);
        uint32_t hh = hb[j];
        if ((idx > B && hh) || idx == B) {
            uint32_t bits = (((pfx0 << 12) | idx) << s3) |
                            (s3 ? (1u << (s3 - 1)) : 0u);   // bin midpoint
            double m = (double)__uint_as_float(bits);
            ds += (idx > B) ? (double)hh * m : (double)need * m;
        }
    }
#pragma unroll
    for (int o = 16; o; o >>= 1) ds += __shfl_down_sync(FULL, ds, o);
    if (lane == 0) dp[t >> 5] = ds;
    __syncthreads();
    if (t == 0) {
        double tot = g_sum;
#pragma unroll
        for (int i = 0; i < 16; i++) tot += dp[i];
        out[0] = (float)(tot / (double)K_SEL);
    }
    __syncthreads();
    if (t == 0) { g_sum = 0.0; g_cntAbove = 0u; g_doneM = 0u; }
}

// ---------------------------------------------------------------------------
extern "C" void kernel_launch(void* const* d_in, const int* in_sizes, int n_in,
                              void* d_out, int out_size) {
    (void)in_sizes; (void)n_in; (void)out_size;
    const float* pred = (const float*)d_in[0];
    const float* tgt  = (const float*)d_in[1];
    float* out = (float*)d_out;

    cudaFuncSetAttribute(kmain, cudaFuncAttributeMaxDynamicSharedMemorySize,
                         SMEM_DYN);
    ksample<<<S_BLOCKS, S_TPB>>>(pred, tgt);
    kmain<<<M_GRID, M_TPB, SMEM_DYN>>>(pred, tgt, out);
}